// round 3
// baseline (speedup 1.0000x reference)
#include <cuda_runtime.h>
#include <cstdint>
#include <cstddef>

#define T_STEPS 1024
#define BATCH   128
#define INDIM   100
#define HID     200
#define NCLS    100
#define NBG     4
#define MB      32
#define NHG     34
#define NHU     6
#define NG      24          // 4 gates * NHU
#define NTHR    128
#define NCTA    (NBG*NHG)   // 136
#define K0      300         // INDIM + HID
#define K1      400         // HID + HID
#define XSTR    36          // smem stride for [k][batch] staging buffer

#define HN_OFF  (T_STEPS*BATCH*NCLS)            // 13,107,200
#define CN_OFF  (HN_OFF + 2*BATCH*HID)          // 13,158,400

// ---- smem layout (floats) ----
// W2_0 : NG*K0 float2 = 14400 floats
// W2_1 : NG*K1 float2 = 19200 floats
// xh   : 500*XSTR     = 18000 floats
// gb0  : 2*NG*MB      = 1536
// gb1  : 2*NG*MB      = 1536
// bias0/1, c0s/c1s
#define OFF_W20 0
#define OFF_W21 (OFF_W20 + NG*K0*2)
#define OFF_XH  (OFF_W21 + NG*K1*2)
#define OFF_GB0 (OFF_XH  + 500*XSTR)
#define OFF_GB1 (OFF_GB0 + 2*NG*MB)
#define OFF_B0  (OFF_GB1 + 2*NG*MB)
#define OFF_B1  (OFF_B0 + NG)
#define OFF_C0  (OFF_B1 + NG)
#define OFF_C1  (OFF_C0 + NHU*MB)
#define SMEM_FLOATS (OFF_C1 + NHU*MB + 16)
#define SMEM_BYTES  (SMEM_FLOATS*4)

#define FC_SMEM_BYTES ((NCLS*HID + 128)*4)

// -------- device scratch --------
__device__ __align__(256) float g_ph0[2][HID*BATCH];
__device__ __align__(256) float g_ph1[2][HID*BATCH];
__device__ __align__(256) float g_y1[(size_t)T_STEPS*HID*BATCH];
__device__ volatile unsigned g_bar[NBG*32];

__global__ void bar_reset_kernel() {
    int i = threadIdx.x;
    if (i < NBG*32) g_bar[i] = 0u;
}

__device__ __forceinline__ float sigm(float x) {
    return __fdividef(1.0f, 1.0f + __expf(-x));
}
__device__ __forceinline__ float tanha(float x) {
    return fmaf(2.0f, sigm(2.0f * x), -1.0f);
}

__device__ __forceinline__ void group_barrier(int bg, unsigned target) {
    __syncthreads();
    if (threadIdx.x == 0) {
        __threadfence();
        atomicAdd((unsigned*)&g_bar[bg*32], 1u);
        while (g_bar[bg*32] < target) { __nanosleep(64); }
        __threadfence();
    }
    __syncthreads();
}

// packed f32x2 fma: acc += w2 * x2 (elementwise on both 32-bit lanes)
#define FMA2(acc, w, x) \
    asm("fma.rn.f32x2 %0, %1, %2, %0;" : "+l"(acc) : "l"(w), "l"(x))

// gates[row][b] partial over one k-half.
// thread tile: 3 rows x 4 batches (2 f32x2 pairs). W2 is float2-duplicated {w,w}.
template<int K, int KHALF, int NITER>
__device__ __forceinline__ void gate_mm2(const float2* __restrict__ W2,
                                         const float* __restrict__ xb,
                                         float* __restrict__ gb,
                                         int r0, int q4, int ks)
{
    unsigned long long a00 = 0ull, a01 = 0ull, a10 = 0ull, a11 = 0ull,
                       a20 = 0ull, a21 = 0ull;
    const float2* w0 = W2 + r0 * K + ks * KHALF;
    const float2* w1 = w0 + K;
    const float2* w2 = w1 + K;
    const float*  xp = xb + ks * KHALF * XSTR + q4;
    #pragma unroll 5
    for (int it = 0; it < NITER; ++it) {
        // each ulonglong2 = two k-values of duplicated-W ({w_k,w_k},{w_k1,w_k1})
        ulonglong2 wv0 = *(const ulonglong2*)(w0 + 2*it);
        ulonglong2 wv1 = *(const ulonglong2*)(w1 + 2*it);
        ulonglong2 wv2 = *(const ulonglong2*)(w2 + 2*it);
        // x: 4 batches at k and k+1 -> two 16B loads, each = 2 batch-pairs
        ulonglong2 xA = *(const ulonglong2*)(xp + (2*it)   * XSTR);
        ulonglong2 xB = *(const ulonglong2*)(xp + (2*it+1) * XSTR);
        FMA2(a00, wv0.x, xA.x); FMA2(a01, wv0.x, xA.y);
        FMA2(a10, wv1.x, xA.x); FMA2(a11, wv1.x, xA.y);
        FMA2(a20, wv2.x, xA.x); FMA2(a21, wv2.x, xA.y);
        FMA2(a00, wv0.y, xB.x); FMA2(a01, wv0.y, xB.y);
        FMA2(a10, wv1.y, xB.x); FMA2(a11, wv1.y, xB.y);
        FMA2(a20, wv2.y, xB.x); FMA2(a21, wv2.y, xB.y);
    }
    float* g = gb + ks * (NG * MB);
    *(ulonglong2*)(g + (r0+0)*MB + q4) = make_ulonglong2(a00, a01);
    *(ulonglong2*)(g + (r0+1)*MB + q4) = make_ulonglong2(a10, a11);
    *(ulonglong2*)(g + (r0+2)*MB + q4) = make_ulonglong2(a20, a21);
}

__global__ void __launch_bounds__(NTHR, 1)
lstm_pers_kernel(const float* __restrict__ inp,  const float* __restrict__ h0in,
                 const float* __restrict__ c0in,
                 const float* __restrict__ Wih0, const float* __restrict__ Whh0,
                 const float* __restrict__ bih0, const float* __restrict__ bhh0,
                 const float* __restrict__ Wih1, const float* __restrict__ Whh1,
                 const float* __restrict__ bih1, const float* __restrict__ bhh1,
                 float* __restrict__ out)
{
    extern __shared__ float sm[];
    float2* W20  = (float2*)(sm + OFF_W20);  // [NG][K0] duplicated
    float2* W21  = (float2*)(sm + OFF_W21);  // [NG][K1] duplicated
    float* xh    = sm + OFF_XH;              // [500][XSTR]
    float* gb0   = sm + OFF_GB0;             // [2][NG][MB]
    float* gb1   = sm + OFF_GB1;
    float* bias0 = sm + OFF_B0;
    float* bias1 = sm + OFF_B1;
    float* c0s   = sm + OFF_C0;              // [NHU][MB]
    float* c1s   = sm + OFF_C1;

    const int tid = threadIdx.x;
    const int bg  = blockIdx.x / NHG;
    const int hg  = blockIdx.x % NHG;
    const int b0  = bg * MB;
    const int hs  = hg * NHU;

    // mm lane decode: bits 0-2 batch-quad, 3-4 rg-low, 5 rg-high, 6 k-half
    // -> each warp = 8 quads x 4 row-groups x ONE k-half (conflict-free LDS)
    const int q4 = (tid & 7) * 4;
    const int rg = ((tid >> 3) & 3) + ((tid >> 5) & 1) * 4;
    const int ks = (tid >> 6) & 1;
    const int r0 = rg * 3;

    // ---- load + duplicate weight slices (resident all run) ----
    for (int i = tid; i < NG * K0; i += NTHR) {
        int c = i / K0, k = i - c * K0;
        int gate = c / NHU, u = c - gate * NHU;
        int j = hs + u, row = gate * HID + j;
        float v = 0.f;
        if (j < HID) v = (k < INDIM) ? Wih0[row * INDIM + k] : Whh0[row * HID + (k - INDIM)];
        W20[c * K0 + k] = make_float2(v, v);
    }
    for (int i = tid; i < NG * K1; i += NTHR) {
        int c = i / K1, k = i - c * K1;
        int gate = c / NHU, u = c - gate * NHU;
        int j = hs + u, row = gate * HID + j;
        float v = 0.f;
        if (j < HID) v = (k < HID) ? Wih1[row * HID + k] : Whh1[row * HID + (k - HID)];
        W21[c * K1 + k] = make_float2(v, v);
    }
    if (tid < NG) {
        int gate = tid / NHU, u = tid - gate * NHU;
        int j = hs + u, row = gate * HID + j;
        bias0[tid] = (j < HID) ? bih0[row] + bhh0[row] : 0.f;
        bias1[tid] = (j < HID) ? bih1[row] + bhh1[row] : 0.f;
    }

    // ---- init c state + publish initial h ----
    for (int e = tid; e < NHU * MB; e += NTHR) {
        int u = e >> 5, b = e & 31, j = hs + u;
        float cv0 = 0.f, cv1 = 0.f;
        if (j < HID) {
            cv0 = c0in[(b0 + b) * HID + j];
            cv1 = c0in[BATCH * HID + (b0 + b) * HID + j];
            g_ph0[1][j * BATCH + b0 + b] = h0in[(b0 + b) * HID + j];
            g_ph1[0][j * BATCH + b0 + b] = h0in[BATCH * HID + (b0 + b) * HID + j];
        }
        c0s[e] = cv0;
        c1s[e] = cv1;
    }

    unsigned bep = 0;
    group_barrier(bg, (++bep) * NHG);

    // ---- main loop: iter i = layer0(step i) + layer1(step i-1) ----
    for (int iter = 0; iter <= T_STEPS; ++iter) {
        // stage x_iter
        if (iter < T_STEPS) {
            const float* xsrc = inp + (size_t)iter * BATCH * INDIM + (size_t)b0 * INDIM;
            for (int idx = tid; idx < MB * INDIM; idx += NTHR) {
                int b = idx / INDIM, k = idx - b * INDIM;
                xh[k * XSTR + b] = __ldg(xsrc + b * INDIM + k);
            }
        }
        // stage h0_{iter-1}
        {
            const float* ph0 = g_ph0[(iter + 1) & 1];
            for (int idx = tid; idx < HID * (MB / 4); idx += NTHR) {
                int j = idx >> 3, q = idx & 7;
                float4 v = __ldcg((const float4*)(ph0 + j * BATCH + b0 + q * 4));
                *(float4*)(&xh[(INDIM + j) * XSTR + q * 4]) = v;
            }
        }
        // stage h1_{iter-2}
        if (iter >= 1) {
            const float* ph1 = g_ph1[(iter + 1) & 1];
            for (int idx = tid; idx < HID * (MB / 4); idx += NTHR) {
                int j = idx >> 3, q = idx & 7;
                float4 v = __ldcg((const float4*)(ph1 + j * BATCH + b0 + q * 4));
                *(float4*)(&xh[(INDIM + HID + j) * XSTR + q * 4]) = v;
            }
        }
        __syncthreads();

        // both layer GEMMs back-to-back, separate gate buffers
        if (iter < T_STEPS)
            gate_mm2<K0, K0/2, K0/4>(W20, xh, gb0, r0, q4, ks);
        if (iter >= 1)
            gate_mm2<K1, K1/2, K1/4>(W21, xh + INDIM * XSTR, gb1, r0, q4, ks);
        __syncthreads();

        // pointwise for both layers (sum the two k-half partials + bias)
        if (iter < T_STEPS) {
            float* hg0 = g_ph0[iter & 1];
            for (int e = tid; e < NHU * MB; e += NTHR) {
                int u = e >> 5, b = e & 31, j = hs + u;
                float gi = gb0[(0*NHU+u)*MB+b] + gb0[NG*MB + (0*NHU+u)*MB+b] + bias0[0*NHU+u];
                float gf = gb0[(1*NHU+u)*MB+b] + gb0[NG*MB + (1*NHU+u)*MB+b] + bias0[1*NHU+u];
                float gg = gb0[(2*NHU+u)*MB+b] + gb0[NG*MB + (2*NHU+u)*MB+b] + bias0[2*NHU+u];
                float go = gb0[(3*NHU+u)*MB+b] + gb0[NG*MB + (3*NHU+u)*MB+b] + bias0[3*NHU+u];
                float c = c0s[e];
                c = sigm(gf) * c + sigm(gi) * tanha(gg);
                float h = sigm(go) * tanha(c);
                c0s[e] = c;
                if (j < HID) hg0[j * BATCH + b0 + b] = h;
            }
        }
        if (iter >= 1) {
            float* hg1 = g_ph1[iter & 1];
            float* yg  = g_y1 + (size_t)(iter - 1) * HID * BATCH;
            for (int e = tid; e < NHU * MB; e += NTHR) {
                int u = e >> 5, b = e & 31, j = hs + u;
                float gi = gb1[(0*NHU+u)*MB+b] + gb1[NG*MB + (0*NHU+u)*MB+b] + bias1[0*NHU+u];
                float gf = gb1[(1*NHU+u)*MB+b] + gb1[NG*MB + (1*NHU+u)*MB+b] + bias1[1*NHU+u];
                float gg = gb1[(2*NHU+u)*MB+b] + gb1[NG*MB + (2*NHU+u)*MB+b] + bias1[2*NHU+u];
                float go = gb1[(3*NHU+u)*MB+b] + gb1[NG*MB + (3*NHU+u)*MB+b] + bias1[3*NHU+u];
                float c = c1s[e];
                c = sigm(gf) * c + sigm(gi) * tanha(gg);
                float h = sigm(go) * tanha(c);
                c1s[e] = c;
                if (j < HID) {
                    hg1[j * BATCH + b0 + b] = h;
                    yg [j * BATCH + b0 + b] = h;
                }
            }
        }
        group_barrier(bg, (++bep) * NHG);
    }

    // ---- epilogue: hn, cn ----
    const float* hf0 = g_ph0[(T_STEPS - 1) & 1];
    const float* hf1 = g_ph1[T_STEPS & 1];
    for (int e = tid; e < NHU * MB; e += NTHR) {
        int u = e >> 5, b = e & 31, j = hs + u;
        if (j < HID) {
            out[HN_OFF + (b0 + b) * HID + j]               = __ldcg(hf0 + j * BATCH + b0 + b);
            out[HN_OFF + BATCH * HID + (b0 + b) * HID + j] = __ldcg(hf1 + j * BATCH + b0 + b);
            out[CN_OFF + (b0 + b) * HID + j]               = c0s[e];
            out[CN_OFF + BATCH * HID + (b0 + b) * HID + j] = c1s[e];
        }
    }
}

// -------- FC head: out[t,b,c] = fcb[c] + sum_h fcW[c][h] * y1[t,h,b] --------
__global__ void __launch_bounds__(256, 1)
fc_kernel(const float* __restrict__ fcW, const float* __restrict__ fcb,
          float* __restrict__ out)
{
    extern __shared__ float s[];
    float* Ws = s;
    float* bs = s + NCLS * HID;
    int tid = threadIdx.x;
    for (int i = tid; i < NCLS * HID; i += 256) Ws[i] = fcW[i];
    if (tid < NCLS) bs[tid] = fcb[tid];
    __syncthreads();

    int t = blockIdx.x;
    const float* y = g_y1 + (size_t)t * HID * BATCH;
    float* o = out + (size_t)t * BATCH * NCLS;

    int bq  = (tid & 31) * 4;
    int cq0 = tid >> 5;
    for (int cq = cq0; cq < 25; cq += 8) {
        int c0 = cq * 4;
        float acc[4][4];
        #pragma unroll
        for (int jc = 0; jc < 4; jc++) {
            float bv = bs[c0 + jc];
            #pragma unroll
            for (int jb = 0; jb < 4; jb++) acc[jc][jb] = bv;
        }
        for (int k = 0; k < HID; ++k) {
            float4 yv = *(const float4*)(y + k * BATCH + bq);
            #pragma unroll
            for (int jc = 0; jc < 4; jc++) {
                float w = Ws[(c0 + jc) * HID + k];
                acc[jc][0] = fmaf(w, yv.x, acc[jc][0]);
                acc[jc][1] = fmaf(w, yv.y, acc[jc][1]);
                acc[jc][2] = fmaf(w, yv.z, acc[jc][2]);
                acc[jc][3] = fmaf(w, yv.w, acc[jc][3]);
            }
        }
        #pragma unroll
        for (int jb = 0; jb < 4; jb++) {
            float4 v = make_float4(acc[0][jb], acc[1][jb], acc[2][jb], acc[3][jb]);
            *(float4*)(o + (bq + jb) * NCLS + c0) = v;
        }
    }
}

extern "C" void kernel_launch(void* const* d_in, const int* in_sizes, int n_in,
                              void* d_out, int out_size)
{
    (void)in_sizes; (void)n_in; (void)out_size;
    const float* inp  = (const float*)d_in[0];
    const float* h0   = (const float*)d_in[1];
    const float* c0   = (const float*)d_in[2];
    const float* Wih0 = (const float*)d_in[3];
    const float* Whh0 = (const float*)d_in[4];
    const float* bih0 = (const float*)d_in[5];
    const float* bhh0 = (const float*)d_in[6];
    const float* Wih1 = (const float*)d_in[7];
    const float* Whh1 = (const float*)d_in[8];
    const float* bih1 = (const float*)d_in[9];
    const float* bhh1 = (const float*)d_in[10];
    const float* fcW  = (const float*)d_in[11];
    const float* fcb  = (const float*)d_in[12];
    float* out = (float*)d_out;

    cudaFuncSetAttribute(lstm_pers_kernel,
                         cudaFuncAttributeMaxDynamicSharedMemorySize, SMEM_BYTES);
    cudaFuncSetAttribute(fc_kernel,
                         cudaFuncAttributeMaxDynamicSharedMemorySize, FC_SMEM_BYTES);

    bar_reset_kernel<<<1, 128>>>();
    lstm_pers_kernel<<<NCTA, NTHR, SMEM_BYTES>>>(inp, h0, c0,
                                                 Wih0, Whh0, bih0, bhh0,
                                                 Wih1, Whh1, bih1, bhh1, out);
    fc_kernel<<<T_STEPS, 256, FC_SMEM_BYTES>>>(fcW, fcb, out);
}

// round 4
// speedup vs baseline: 1.3554x; 1.3554x over previous
#include <cuda_runtime.h>
#include <cstdint>
#include <cstddef>

#define T_STEPS 1024
#define BATCH   128
#define INDIM   100
#define HID     200
#define NCLS    100
#define NBG     8           // batch groups
#define MB      16          // batch per group
#define NHG     17          // hidden groups per batch group
#define NHU     12          // hidden units per CTA (17*12=204, 4 dead rows)
#define NG      48          // gate rows per CTA (4 gates * NHU)
#define NTHR    256
#define NCTA    (NBG*NHG)   // 136
#define XSTR    20          // smem stride of [k][b] staging buffer

#define HN_OFF  (T_STEPS*BATCH*NCLS)
#define CN_OFF  (HN_OFF + 2*BATCH*HID)

// ---- smem float offsets ----
#define OFF_W0  0                       // [NG][300]
#define OFF_W1  14400                   // [NG][400]
#define OFF_XH  33600                   // [500][XSTR] rows: 0-99 x, 100-299 h0, 300-499 h1
#define OFF_GB0 43600                   // [2][NG][MB]
#define OFF_GB1 45136
#define OFF_XA  46672                   // [2][NG][MB] x-projection partials
#define OFF_B0  48208
#define OFF_B1  48256
#define OFF_C0  48304                   // [NHU][MB]
#define OFF_C1  48496
#define SMEM_FLOATS 48704
#define SMEM_BYTES  (SMEM_FLOATS*4)     // ~190 KB

// FC-phase smem reuse
#define OFF_FW  0        // [100][200]
#define OFF_FB  20000
#define OFF_YS  20128    // [50][128] y chunk

// -------- device scratch --------
__device__ __align__(256) float g_ph0[2][HID*BATCH];
__device__ __align__(256) float g_ph1[2][HID*BATCH];
__device__ __align__(256) float g_y1[(size_t)T_STEPS*HID*BATCH];
__device__ unsigned g_bar[NBG*32];   // per-group counters, 128B apart
__device__ unsigned g_gbar;          // global barrier
__device__ unsigned g_ack;           // end-of-kernel ack for reset

__device__ __forceinline__ float sigm(float x) {
    return __fdividef(1.0f, 1.0f + __expf(-x));
}
__device__ __forceinline__ float tanha(float x) {
    return fmaf(2.0f, sigm(2.0f * x), -1.0f);
}

__device__ __forceinline__ void bar_arrive(unsigned* p) {
    unsigned one = 1u;
    asm volatile("red.release.gpu.global.add.u32 [%0], %1;" :: "l"(p), "r"(one) : "memory");
}
__device__ __forceinline__ unsigned ld_acq(const unsigned* p) {
    unsigned v;
    asm volatile("ld.acquire.gpu.global.u32 %0, [%1];" : "=r"(v) : "l"(p) : "memory");
    return v;
}
__device__ __forceinline__ void cpa16(uint32_t dst, const void* src) {
    asm volatile("cp.async.cg.shared.global [%0], [%1], 16;" :: "r"(dst), "l"(src) : "memory");
}
__device__ __forceinline__ void cpa_wait() {
    asm volatile("cp.async.commit_group;\n\tcp.async.wait_group 0;" ::: "memory");
}

// gates[r0..r0+2][bb..bb+1] partial over one k-half (KH long), x in smem [k][b]
template<int KH>
__device__ __forceinline__ void gate_mm(const float* __restrict__ W, int wst,
                                        const float* __restrict__ xp0,
                                        float* __restrict__ gbuf,
                                        int r0, int bb, int ks)
{
    const float* w0 = W + r0 * wst + ks * KH;
    const float* w1 = w0 + wst;
    const float* w2 = w1 + wst;
    const float* xp = xp0 + ks * KH * XSTR + bb;
    float a00=0.f,a01=0.f,a10=0.f,a11=0.f,a20=0.f,a21=0.f;
    #pragma unroll 10
    for (int k = 0; k < KH; k += 2) {
        float2 xa = *(const float2*)(xp + k * XSTR);
        float2 xc = *(const float2*)(xp + (k + 1) * XSTR);
        float2 wa = *(const float2*)(w0 + k);
        float2 wb = *(const float2*)(w1 + k);
        float2 wc = *(const float2*)(w2 + k);
        a00=fmaf(wa.x,xa.x,a00); a01=fmaf(wa.x,xa.y,a01);
        a10=fmaf(wb.x,xa.x,a10); a11=fmaf(wb.x,xa.y,a11);
        a20=fmaf(wc.x,xa.x,a20); a21=fmaf(wc.x,xa.y,a21);
        a00=fmaf(wa.y,xc.x,a00); a01=fmaf(wa.y,xc.y,a01);
        a10=fmaf(wb.y,xc.x,a10); a11=fmaf(wb.y,xc.y,a11);
        a20=fmaf(wc.y,xc.x,a20); a21=fmaf(wc.y,xc.y,a21);
    }
    float* g = gbuf + ks * (NG * MB);
    g[(r0+0)*MB+bb]=a00; g[(r0+0)*MB+bb+1]=a01;
    g[(r0+1)*MB+bb]=a10; g[(r0+1)*MB+bb+1]=a11;
    g[(r0+2)*MB+bb]=a20; g[(r0+2)*MB+bb+1]=a21;
}

__global__ void __launch_bounds__(NTHR, 1)
lstm_all_kernel(const float* __restrict__ inp,  const float* __restrict__ h0in,
                const float* __restrict__ c0in,
                const float* __restrict__ Wih0, const float* __restrict__ Whh0,
                const float* __restrict__ bih0, const float* __restrict__ bhh0,
                const float* __restrict__ Wih1, const float* __restrict__ Whh1,
                const float* __restrict__ bih1, const float* __restrict__ bhh1,
                const float* __restrict__ fcW,  const float* __restrict__ fcb,
                float* __restrict__ out)
{
    extern __shared__ float sm[];
    float* W0s   = sm + OFF_W0;
    float* W1s   = sm + OFF_W1;
    float* xh    = sm + OFF_XH;
    float* gb0   = sm + OFF_GB0;
    float* gb1   = sm + OFF_GB1;
    float* xac   = sm + OFF_XA;
    float* bias0 = sm + OFF_B0;
    float* bias1 = sm + OFF_B1;
    float* c0s   = sm + OFF_C0;
    float* c1s   = sm + OFF_C1;

    const int tid = threadIdx.x;
    const int bg  = blockIdx.x / NHG;
    const int hg  = blockIdx.x % NHG;
    const int b0  = bg * MB;
    const int hs  = hg * NHU;
    const uint32_t smb = (uint32_t)__cvta_generic_to_shared(sm);

    // mm lane decode: bb pair (bits 0-2), row-group (bits 3-6), k-half (bit 7)
    const int bb = (tid & 7) * 2;
    const int r0 = ((tid >> 3) & 15) * 3;
    const int ks = (tid >> 7) & 1;

    // ---- resident weight slices ----
    for (int i = tid; i < NG * 300; i += NTHR) {
        int c = i / 300, k = i - c * 300;
        int gate = c / NHU, u = c - gate * NHU;
        int j = hs + u, row = gate * HID + j;
        float v = 0.f;
        if (j < HID) v = (k < INDIM) ? Wih0[row * INDIM + k] : Whh0[row * HID + (k - INDIM)];
        W0s[c * 300 + k] = v;
    }
    for (int i = tid; i < NG * 400; i += NTHR) {
        int c = i / 400, k = i - c * 400;
        int gate = c / NHU, u = c - gate * NHU;
        int j = hs + u, row = gate * HID + j;
        float v = 0.f;
        if (j < HID) v = (k < HID) ? Wih1[row * HID + k] : Whh1[row * HID + (k - HID)];
        W1s[c * 400 + k] = v;
    }
    if (tid < NG) {
        int gate = tid / NHU, u = tid - gate * NHU;
        int j = hs + u, row = gate * HID + j;
        bias0[tid] = (j < HID) ? bih0[row] + bhh0[row] : 0.f;
        bias1[tid] = (j < HID) ? bih1[row] + bhh1[row] : 0.f;
    }

    // ---- init c state, publish initial h ----
    if (tid < NHU * MB) {
        int e = tid, u = e >> 4, b = e & 15, j = hs + u;
        float cv0 = 0.f, cv1 = 0.f;
        if (j < HID) {
            cv0 = c0in[(b0 + b) * HID + j];
            cv1 = c0in[BATCH * HID + (b0 + b) * HID + j];
            g_ph0[1][j * BATCH + b0 + b] = h0in[(b0 + b) * HID + j];
            g_ph1[0][j * BATCH + b0 + b] = h0in[BATCH * HID + (b0 + b) * HID + j];
        }
        c0s[e] = cv0;
        c1s[e] = cv1;
    }

    // ---- prologue: stage x(0), compute xacc(0) ----
    {
        const float* xsrc = inp + (size_t)b0 * INDIM;
        for (int idx = tid; idx < MB * INDIM; idx += NTHR) {
            int b = idx / INDIM, k = idx - b * INDIM;
            xh[k * XSTR + b] = __ldg(xsrc + b * INDIM + k);
        }
    }
    __syncthreads();
    gate_mm<50>(W0s, 300, xh, xac, r0, bb, ks);
    __syncthreads();

    unsigned* gbar = &g_bar[bg * 32];
    unsigned ep = 1;
    if (tid == 0) {
        bar_arrive(gbar);                       // publishes h inits + covers nothing else yet
        while (ld_acq(gbar) < ep * NHG) {}
    }
    __syncthreads();

    // ---- main loop: iter i = layer0(step i) + layer1(step i-1) ----
    for (int it = 0; it <= T_STEPS; ++it) {
        // async-stage h0(it-1) (rows 100+), h1(it-2) (rows 300+)
        {
            const float* ph0 = g_ph0[(it + 1) & 1];
            for (int idx = tid; idx < HID * 4; idx += NTHR) {
                int j = idx >> 2, q = idx & 3;
                cpa16(smb + (OFF_XH + (INDIM + j) * XSTR + q * 4) * 4,
                      ph0 + j * BATCH + b0 + q * 4);
            }
            if (it >= 1) {
                const float* ph1 = g_ph1[(it + 1) & 1];
                for (int idx = tid; idx < HID * 4; idx += NTHR) {
                    int j = idx >> 2, q = idx & 3;
                    cpa16(smb + (OFF_XH + (INDIM + HID + j) * XSTR + q * 4) * 4,
                          ph1 + j * BATCH + b0 + q * 4);
                }
            }
            cpa_wait();
        }
        __syncthreads();

        if (it < T_STEPS)
            gate_mm<100>(W0s + INDIM, 300, xh + INDIM * XSTR, gb0, r0, bb, ks); // Whh0 part
        if (it >= 1)
            gate_mm<200>(W1s, 400, xh + INDIM * XSTR, gb1, r0, bb, ks);         // full layer1
        __syncthreads();

        // pointwise
        if (tid < NHU * MB) {
            int e = tid, u = e >> 4, b = e & 15, j = hs + u;
            if (it < T_STEPS) {
                float gi = gb0[u*MB+b]        + gb0[NG*MB + u*MB+b]
                         + xac[u*MB+b]        + xac[NG*MB + u*MB+b]        + bias0[u];
                float gf = gb0[(NHU+u)*MB+b]  + gb0[NG*MB + (NHU+u)*MB+b]
                         + xac[(NHU+u)*MB+b]  + xac[NG*MB + (NHU+u)*MB+b]  + bias0[NHU+u];
                float gg = gb0[(2*NHU+u)*MB+b]+ gb0[NG*MB + (2*NHU+u)*MB+b]
                         + xac[(2*NHU+u)*MB+b]+ xac[NG*MB + (2*NHU+u)*MB+b]+ bias0[2*NHU+u];
                float go = gb0[(3*NHU+u)*MB+b]+ gb0[NG*MB + (3*NHU+u)*MB+b]
                         + xac[(3*NHU+u)*MB+b]+ xac[NG*MB + (3*NHU+u)*MB+b]+ bias0[3*NHU+u];
                float c = c0s[e];
                c = sigm(gf) * c + sigm(gi) * tanha(gg);
                float h = sigm(go) * tanha(c);
                c0s[e] = c;
                if (j < HID) g_ph0[it & 1][j * BATCH + b0 + b] = h;
            }
            if (it >= 1) {
                float gi = gb1[u*MB+b]         + gb1[NG*MB + u*MB+b]         + bias1[u];
                float gf = gb1[(NHU+u)*MB+b]   + gb1[NG*MB + (NHU+u)*MB+b]   + bias1[NHU+u];
                float gg = gb1[(2*NHU+u)*MB+b] + gb1[NG*MB + (2*NHU+u)*MB+b] + bias1[2*NHU+u];
                float go = gb1[(3*NHU+u)*MB+b] + gb1[NG*MB + (3*NHU+u)*MB+b] + bias1[3*NHU+u];
                float c = c1s[e];
                c = sigm(gf) * c + sigm(gi) * tanha(gg);
                float h = sigm(go) * tanha(c);
                c1s[e] = c;
                if (j < HID) {
                    g_ph1[it & 1][j * BATCH + b0 + b] = h;
                    g_y1[(size_t)(it - 1) * HID * BATCH + j * BATCH + b0 + b] = h;
                }
            }
        }
        if (it == T_STEPS) break;          // no further consumers; skip last barrier
        __syncthreads();

        ep++;
        if (tid == 0) bar_arrive(gbar);

        // ---- barrier-shadow work: stage x(it+1) + xacc(it+1) ----
        if (it + 1 < T_STEPS) {
            const float* xsrc = inp + (size_t)(it + 1) * BATCH * INDIM + (size_t)b0 * INDIM;
            for (int idx = tid; idx < MB * INDIM; idx += NTHR) {
                int b = idx / INDIM, k = idx - b * INDIM;
                xh[k * XSTR + b] = __ldg(xsrc + b * INDIM + k);
            }
            __syncthreads();
            gate_mm<50>(W0s, 300, xh, xac, r0, bb, ks);
        }

        if (tid == 0) { while (ld_acq(gbar) < ep * NHG) {} }
        __syncthreads();
    }

    // ---- epilogue: hn, cn (own rows/batches only) ----
    if (tid < NHU * MB) {
        int e = tid, u = e >> 4, b = e & 15, j = hs + u;
        if (j < HID) {
            out[HN_OFF + (b0 + b) * HID + j]               = __ldcg(&g_ph0[(T_STEPS - 1) & 1][j * BATCH + b0 + b]);
            out[HN_OFF + BATCH * HID + (b0 + b) * HID + j] = __ldcg(&g_ph1[T_STEPS & 1][j * BATCH + b0 + b]);
            out[CN_OFF + (b0 + b) * HID + j]               = c0s[e];
            out[CN_OFF + BATCH * HID + (b0 + b) * HID + j] = c1s[e];
        }
    }
    __syncthreads();

    // ---- global barrier before FC ----
    if (tid == 0) {
        bar_arrive(&g_gbar);
        while (ld_acq(&g_gbar) < NCTA) {}
    }
    __syncthreads();

    // ---- FC phase: out[t,b,c] = fcb[c] + sum_h fcW[c][h] * y1[t,h,b] ----
    {
        float* fws = sm + OFF_FW;   // [100][200]
        float* fbs = sm + OFF_FB;   // [100]
        float* ys  = sm + OFF_YS;   // [50][128]
        for (int i = tid; i < NCLS * HID; i += NTHR) fws[i] = fcW[i];
        if (tid < NCLS) fbs[tid] = fcb[tid];
        __syncthreads();

        const int bq = (tid & 31) * 4;
        const int cg = tid >> 5;              // 0..7
        for (int tt = 0; tt < 8; ++tt) {
            int t = blockIdx.x * 8 + tt;
            if (t >= T_STEPS) break;
            const float* y = g_y1 + (size_t)t * HID * BATCH;
            float acc[4][4][4];               // [qi][jc][jb]
            #pragma unroll
            for (int qi = 0; qi < 4; qi++) {
                int cq = cg + 8 * qi;
                #pragma unroll
                for (int jc = 0; jc < 4; jc++) {
                    float bv = (cq < 25) ? fbs[cq * 4 + jc] : 0.f;
                    #pragma unroll
                    for (int jb = 0; jb < 4; jb++) acc[qi][jc][jb] = bv;
                }
            }
            for (int kc = 0; kc < 4; ++kc) {
                __syncthreads();
                for (int i = tid; i < 50 * 32; i += NTHR) {
                    int k = i >> 5, q = i & 31;
                    *(float4*)&ys[k * 128 + q * 4] =
                        __ldcg((const float4*)(y + (size_t)(kc * 50 + k) * BATCH + q * 4));
                }
                __syncthreads();
                for (int k = 0; k < 50; ++k) {
                    float4 yv = *(const float4*)&ys[k * 128 + bq];
                    #pragma unroll
                    for (int qi = 0; qi < 4; qi++) {
                        int cq = cg + 8 * qi;
                        if (cq < 25) {
                            #pragma unroll
                            for (int jc = 0; jc < 4; jc++) {
                                float w = fws[(cq * 4 + jc) * HID + kc * 50 + k];
                                acc[qi][jc][0] = fmaf(w, yv.x, acc[qi][jc][0]);
                                acc[qi][jc][1] = fmaf(w, yv.y, acc[qi][jc][1]);
                                acc[qi][jc][2] = fmaf(w, yv.z, acc[qi][jc][2]);
                                acc[qi][jc][3] = fmaf(w, yv.w, acc[qi][jc][3]);
                            }
                        }
                    }
                }
            }
            float* o = out + (size_t)t * BATCH * NCLS;
            #pragma unroll
            for (int qi = 0; qi < 4; qi++) {
                int cq = cg + 8 * qi;
                if (cq < 25) {
                    #pragma unroll
                    for (int jb = 0; jb < 4; jb++) {
                        float4 v = make_float4(acc[qi][0][jb], acc[qi][1][jb],
                                               acc[qi][2][jb], acc[qi][3][jb]);
                        *(float4*)(o + (bq + jb) * NCLS + cq * 4) = v;
                    }
                }
            }
        }
    }

    // ---- reset-free counter cleanup ----
    __syncthreads();
    if (tid == 0) {
        bar_arrive(&g_ack);
        if (blockIdx.x == 0) {
            while (ld_acq(&g_ack) < NCTA) {}
            for (int i = 0; i < NBG; i++) *(volatile unsigned*)&g_bar[i * 32] = 0u;
            *(volatile unsigned*)&g_gbar = 0u;
            *(volatile unsigned*)&g_ack  = 0u;
        }
    }
}

extern "C" void kernel_launch(void* const* d_in, const int* in_sizes, int n_in,
                              void* d_out, int out_size)
{
    (void)in_sizes; (void)n_in; (void)out_size;
    const float* inp  = (const float*)d_in[0];
    const float* h0   = (const float*)d_in[1];
    const float* c0   = (const float*)d_in[2];
    const float* Wih0 = (const float*)d_in[3];
    const float* Whh0 = (const float*)d_in[4];
    const float* bih0 = (const float*)d_in[5];
    const float* bhh0 = (const float*)d_in[6];
    const float* Wih1 = (const float*)d_in[7];
    const float* Whh1 = (const float*)d_in[8];
    const float* bih1 = (const float*)d_in[9];
    const float* bhh1 = (const float*)d_in[10];
    const float* fcW  = (const float*)d_in[11];
    const float* fcb  = (const float*)d_in[12];
    float* out = (float*)d_out;

    cudaFuncSetAttribute(lstm_all_kernel,
                         cudaFuncAttributeMaxDynamicSharedMemorySize, SMEM_BYTES);
    lstm_all_kernel<<<NCTA, NTHR, SMEM_BYTES>>>(inp, h0, c0,
                                                Wih0, Whh0, bih0, bhh0,
                                                Wih1, Whh1, bih1, bhh1,
                                                fcW, fcb, out);
}

// round 6
// speedup vs baseline: 1.7230x; 1.2712x over previous
#include <cuda_runtime.h>
#include <cstdint>
#include <cstddef>

#define T_STEPS 1024
#define BATCH   128
#define INDIM   100
#define HID     200
#define NCLS    100
#define NBG     8           // batch groups
#define MB      16          // batch per group
#define NHG     17          // hidden groups per batch group
#define NHU     12          // hidden units per CTA
#define NG      48          // gate rows per CTA
#define NTHR    512
#define NCTA    (NBG*NHG)   // 136
#define XSTR    20          // smem stride of [k][b] staging buffer
#define W1ST    404         // padded W1 row stride (bank-conflict-free)

#define HN_OFF  (T_STEPS*BATCH*NCLS)
#define CN_OFF  (HN_OFF + 2*BATCH*HID)

// ---- smem float offsets ----
#define OFF_W0  0                        // [NG][300]
#define OFF_W1  14400                    // [NG][404]
#define OFF_XH  33792                    // [500][XSTR]
#define OFF_GB0 43792                    // [4][NG][MB]
#define OFF_GB1 46864                    // [8][NG][MB]
#define OFF_XA  53008                    // [2][NG][MB]
#define OFF_B0  54544
#define OFF_B1  54592
#define OFF_C0  54640                    // [NHU][MB]
#define OFF_C1  54832
#define SMEM_FLOATS 55040
#define SMEM_BYTES  (SMEM_FLOATS*4)      // 220,160 B

// FC-phase smem reuse
#define OFF_FW  0        // [100][200]
#define OFF_FB  20000
#define OFF_YS  20128    // [50][128]

// -------- device scratch --------
__device__ __align__(256) float g_ph0[2][HID*BATCH];
__device__ __align__(256) float g_ph1[2][HID*BATCH];
__device__ __align__(256) float g_y1[(size_t)T_STEPS*HID*BATCH];
__device__ unsigned g_bar[NBG*32];
__device__ unsigned g_gbar;
__device__ unsigned g_ack;

__device__ __forceinline__ float sigm(float x) {
    return __fdividef(1.0f, 1.0f + __expf(-x));
}
__device__ __forceinline__ float tanha(float x) {
    return fmaf(2.0f, sigm(2.0f * x), -1.0f);
}

__device__ __forceinline__ void bar_arrive(unsigned* p) {
    unsigned one = 1u;
    asm volatile("red.release.gpu.global.add.u32 [%0], %1;" :: "l"(p), "r"(one) : "memory");
}
__device__ __forceinline__ unsigned ld_acq(const unsigned* p) {
    unsigned v;
    asm volatile("ld.acquire.gpu.global.u32 %0, [%1];" : "=r"(v) : "l"(p) : "memory");
    return v;
}
__device__ __forceinline__ void cpa16(uint32_t dst, const void* src) {
    asm volatile("cp.async.cg.shared.global [%0], [%1], 16;" :: "r"(dst), "l"(src) : "memory");
}
__device__ __forceinline__ void cpa_wait() {
    asm volatile("cp.async.commit_group;\n\tcp.async.wait_group 0;" ::: "memory");
}

// gates[r0..r0+2][bq..bq+3] partial over k-chunk ks of length KH
template<int KH, int WST>
__device__ __forceinline__ void gate_mm4(const float* __restrict__ W,
                                         const float* __restrict__ xp0,
                                         float* __restrict__ gbuf,
                                         int r0, int bq, int ks)
{
    const float* w0 = W + r0 * WST + ks * KH;
    const float* w1 = w0 + WST;
    const float* w2 = w1 + WST;
    const float* xp = xp0 + ks * KH * XSTR + bq;
    float a00=0.f,a01=0.f,a02=0.f,a03=0.f;
    float a10=0.f,a11=0.f,a12=0.f,a13=0.f;
    float a20=0.f,a21=0.f,a22=0.f,a23=0.f;
    #pragma unroll 5
    for (int k = 0; k < KH; k += 2) {
        float4 xa = *(const float4*)(xp + k * XSTR);
        float4 xb = *(const float4*)(xp + (k + 1) * XSTR);
        float2 wa = *(const float2*)(w0 + k);
        float2 wb = *(const float2*)(w1 + k);
        float2 wc = *(const float2*)(w2 + k);
        a00=fmaf(wa.x,xa.x,a00); a01=fmaf(wa.x,xa.y,a01); a02=fmaf(wa.x,xa.z,a02); a03=fmaf(wa.x,xa.w,a03);
        a10=fmaf(wb.x,xa.x,a10); a11=fmaf(wb.x,xa.y,a11); a12=fmaf(wb.x,xa.z,a12); a13=fmaf(wb.x,xa.w,a13);
        a20=fmaf(wc.x,xa.x,a20); a21=fmaf(wc.x,xa.y,a21); a22=fmaf(wc.x,xa.z,a22); a23=fmaf(wc.x,xa.w,a23);
        a00=fmaf(wa.y,xb.x,a00); a01=fmaf(wa.y,xb.y,a01); a02=fmaf(wa.y,xb.z,a02); a03=fmaf(wa.y,xb.w,a03);
        a10=fmaf(wb.y,xb.x,a10); a11=fmaf(wb.y,xb.y,a11); a12=fmaf(wb.y,xb.z,a12); a13=fmaf(wb.y,xb.w,a13);
        a20=fmaf(wc.y,xb.x,a20); a21=fmaf(wc.y,xb.y,a21); a22=fmaf(wc.y,xb.z,a22); a23=fmaf(wc.y,xb.w,a23);
    }
    float* g = gbuf + ks * (NG * MB);
    *(float4*)(g + (r0+0)*MB + bq) = make_float4(a00,a01,a02,a03);
    *(float4*)(g + (r0+1)*MB + bq) = make_float4(a10,a11,a12,a13);
    *(float4*)(g + (r0+2)*MB + bq) = make_float4(a20,a21,a22,a23);
}

__global__ void __launch_bounds__(NTHR, 1)
lstm_all_kernel(const float* __restrict__ inp,  const float* __restrict__ h0in,
                const float* __restrict__ c0in,
                const float* __restrict__ Wih0, const float* __restrict__ Whh0,
                const float* __restrict__ bih0, const float* __restrict__ bhh0,
                const float* __restrict__ Wih1, const float* __restrict__ Whh1,
                const float* __restrict__ bih1, const float* __restrict__ bhh1,
                const float* __restrict__ fcW,  const float* __restrict__ fcb,
                float* __restrict__ out)
{
    extern __shared__ float sm[];
    float* W0s   = sm + OFF_W0;
    float* W1s   = sm + OFF_W1;
    float* xh    = sm + OFF_XH;
    float* gb0   = sm + OFF_GB0;
    float* gb1   = sm + OFF_GB1;
    float* xac   = sm + OFF_XA;
    float* bias0 = sm + OFF_B0;
    float* bias1 = sm + OFF_B1;
    float* c0s   = sm + OFF_C0;
    float* c1s   = sm + OFF_C1;

    const int tid = threadIdx.x;
    const int bg  = blockIdx.x / NHG;
    const int hg  = blockIdx.x % NHG;
    const int b0  = bg * MB;
    const int hs  = hg * NHU;
    const uint32_t smb = (uint32_t)__cvta_generic_to_shared(sm);

    // mm decode: cell in 0..63 -> 16 row-groups x 4 batch-quads; ksplit = tid>>6
    const int cell = tid & 63;
    const int bq   = (cell & 3) * 4;
    const int r0   = (cell >> 2) * 3;
    const int ksp  = tid >> 6;            // 0..7

    // ---- resident weight slices ----
    for (int i = tid; i < NG * 300; i += NTHR) {
        int c = i / 300, k = i - c * 300;
        int gate = c / NHU, u = c - gate * NHU;
        int j = hs + u, row = gate * HID + j;
        float v = 0.f;
        if (j < HID) v = (k < INDIM) ? Wih0[row * INDIM + k] : Whh0[row * HID + (k - INDIM)];
        W0s[c * 300 + k] = v;
    }
    for (int i = tid; i < NG * 400; i += NTHR) {
        int c = i / 400, k = i - c * 400;
        int gate = c / NHU, u = c - gate * NHU;
        int j = hs + u, row = gate * HID + j;
        float v = 0.f;
        if (j < HID) v = (k < HID) ? Wih1[row * HID + k] : Whh1[row * HID + (k - HID)];
        W1s[c * W1ST + k] = v;
    }
    if (tid < NG) {
        int gate = tid / NHU, u = tid - gate * NHU;
        int j = hs + u, row = gate * HID + j;
        bias0[tid] = (j < HID) ? bih0[row] + bhh0[row] : 0.f;
        bias1[tid] = (j < HID) ? bih1[row] + bhh1[row] : 0.f;
    }

    // ---- init c state, publish initial h ----
    if (tid < NHU * MB) {
        int e = tid, u = e >> 4, b = e & 15, j = hs + u;
        float cv0 = 0.f, cv1 = 0.f;
        if (j < HID) {
            cv0 = c0in[(b0 + b) * HID + j];
            cv1 = c0in[BATCH * HID + (b0 + b) * HID + j];
            g_ph0[1][j * BATCH + b0 + b] = h0in[(b0 + b) * HID + j];
            g_ph1[0][j * BATCH + b0 + b] = h0in[BATCH * HID + (b0 + b) * HID + j];
        }
        c0s[e] = cv0;
        c1s[e] = cv1;
    }

    // ---- prologue: stage x(0), xacc(0) ----
    {
        const float* xsrc = inp + (size_t)b0 * INDIM;
        for (int idx = tid; idx < MB * INDIM; idx += NTHR) {
            int b = idx / INDIM, k = idx - b * INDIM;
            xh[k * XSTR + b] = __ldg(xsrc + b * INDIM + k);
        }
    }
    __syncthreads();
    if (tid < 128) gate_mm4<50, 300>(W0s, xh, xac, r0, bq, ksp);
    __syncthreads();

    unsigned* gbar = &g_bar[bg * 32];
    unsigned ep = 1;
    if (tid == 0) {
        bar_arrive(gbar);
        while (ld_acq(gbar) < ep * NHG) {}
    }
    __syncthreads();

    // ---- main loop: iter it = layer0(step it) + layer1(step it-1) ----
    for (int it = 0; it <= T_STEPS; ++it) {
        // async-stage h0(it-1) -> rows 100-299, h1(it-2) -> rows 300-499
        {
            const float* ph0 = g_ph0[(it + 1) & 1];
            const float* ph1 = g_ph1[(it + 1) & 1];
            int tot = (it >= 1) ? 1600 : 800;
            for (int idx = tid; idx < tot; idx += NTHR) {
                int a = idx >> 2, q = idx & 3;          // a in 0..399 over [h0;h1]
                const float* src = (a < HID) ? (ph0 + a * BATCH)
                                             : (ph1 + (a - HID) * BATCH);
                cpa16(smb + (OFF_XH + (INDIM + a) * XSTR + q * 4) * 4,
                      src + b0 + q * 4);
            }
            cpa_wait();
        }
        __syncthreads();

        if (it < T_STEPS && tid < 256)
            gate_mm4<50, 300>(W0s + INDIM, xh + INDIM * XSTR, gb0, r0, bq, ksp); // Whh0
        if (it >= 1)
            gate_mm4<50, W1ST>(W1s, xh + INDIM * XSTR, gb1, r0, bq, ksp);        // layer1 full
        __syncthreads();

        // ---- pointwise (layer0 on t<192, layer1 on 192<=t<384) ----
        if (it < T_STEPS && tid < 192) {
            int e = tid, u = e >> 4, b = e & 15, j = hs + u;
            float gv[4];
            #pragma unroll
            for (int g = 0; g < 4; ++g) {
                int rr = g * NHU + u;
                float v = bias0[rr];
                #pragma unroll
                for (int s = 0; s < 4; ++s) v += gb0[s * (NG*MB) + rr * MB + b];
                v += xac[rr * MB + b] + xac[NG*MB + rr * MB + b];
                gv[g] = v;
            }
            float c = c0s[e];
            c = sigm(gv[1]) * c + sigm(gv[0]) * tanha(gv[2]);
            float h = sigm(gv[3]) * tanha(c);
            c0s[e] = c;
            if (j < HID) g_ph0[it & 1][j * BATCH + b0 + b] = h;
        }
        if (it >= 1 && tid >= 192 && tid < 384) {
            int e = tid - 192, u = e >> 4, b = e & 15, j = hs + u;
            float gv[4];
            #pragma unroll
            for (int g = 0; g < 4; ++g) {
                int rr = g * NHU + u;
                float v = bias1[rr];
                #pragma unroll
                for (int s = 0; s < 8; ++s) v += gb1[s * (NG*MB) + rr * MB + b];
                gv[g] = v;
            }
            float c = c1s[e];
            c = sigm(gv[1]) * c + sigm(gv[0]) * tanha(gv[2]);
            float h = sigm(gv[3]) * tanha(c);
            c1s[e] = c;
            if (j < HID) {
                g_ph1[it & 1][j * BATCH + b0 + b] = h;
                g_y1[(size_t)(it - 1) * HID * BATCH + j * BATCH + b0 + b] = h;
            }
        }
        if (it == T_STEPS) break;
        __syncthreads();

        ep++;
        if (tid == 0) bar_arrive(gbar);

        // ---- barrier-shadow: stage x(it+1), xacc(it+1) ----
        if (it + 1 < T_STEPS) {
            const float* xsrc = inp + (size_t)(it + 1) * BATCH * INDIM + (size_t)b0 * INDIM;
            for (int idx = tid; idx < MB * INDIM; idx += NTHR) {
                int b = idx / INDIM, k = idx - b * INDIM;
                xh[k * XSTR + b] = __ldg(xsrc + b * INDIM + k);
            }
            __syncthreads();
            if (tid < 128) gate_mm4<50, 300>(W0s, xh, xac, r0, bq, ksp);
        }

        if (tid == 0) { while (ld_acq(gbar) < ep * NHG) {} }
        __syncthreads();
    }

    // RACE FIX: final layer1 pointwise (tid 192-383) must be visible to the
    // epilogue readers (tid 0-191) — this sync was missing in round 5.
    __syncthreads();

    // ---- epilogue: hn, cn ----
    if (tid < NHU * MB) {
        int e = tid, u = e >> 4, b = e & 15, j = hs + u;
        if (j < HID) {
            out[HN_OFF + (b0 + b) * HID + j]               = __ldcg(&g_ph0[(T_STEPS - 1) & 1][j * BATCH + b0 + b]);
            out[HN_OFF + BATCH * HID + (b0 + b) * HID + j] = __ldcg(&g_ph1[T_STEPS & 1][j * BATCH + b0 + b]);
            out[CN_OFF + (b0 + b) * HID + j]               = c0s[e];
            out[CN_OFF + BATCH * HID + (b0 + b) * HID + j] = c1s[e];
        }
    }
    __syncthreads();

    // ---- global barrier before FC ----
    if (tid == 0) {
        bar_arrive(&g_gbar);
        while (ld_acq(&g_gbar) < NCTA) {}
    }
    __syncthreads();

    // ---- FC phase: out[t,b,c] = fcb[c] + sum_h fcW[c][h] * y1[t,h,b] ----
    {
        float* fws = sm + OFF_FW;
        float* fbs = sm + OFF_FB;
        float* ys  = sm + OFF_YS;
        for (int i = tid; i < NCLS * HID; i += NTHR) fws[i] = fcW[i];
        if (tid < NCLS) fbs[tid] = fcb[tid];
        __syncthreads();

        const int bqf = (tid & 31) * 4;
        const int cg  = tid >> 5;              // 0..15
        for (int tt = 0; tt < 8; ++tt) {
            int t = blockIdx.x * 8 + tt;
            if (t >= T_STEPS) break;
            const float* y = g_y1 + (size_t)t * HID * BATCH;
            float acc[2][4][4];
            #pragma unroll
            for (int qi = 0; qi < 2; qi++) {
                int cq = cg + 16 * qi;
                #pragma unroll
                for (int jc = 0; jc < 4; jc++) {
                    float bv = (cq < 25) ? fbs[cq * 4 + jc] : 0.f;
                    #pragma unroll
                    for (int jb = 0; jb < 4; jb++) acc[qi][jc][jb] = bv;
                }
            }
            for (int kc = 0; kc < 4; ++kc) {
                __syncthreads();
                for (int i = tid; i < 50 * 32; i += NTHR) {
                    int k = i >> 5, q = i & 31;
                    *(float4*)&ys[k * 128 + q * 4] =
                        __ldcg((const float4*)(y + (size_t)(kc * 50 + k) * BATCH + q * 4));
                }
                __syncthreads();
                for (int k = 0; k < 50; ++k) {
                    float4 yv = *(const float4*)&ys[k * 128 + bqf];
                    #pragma unroll
                    for (int qi = 0; qi < 2; qi++) {
                        int cq = cg + 16 * qi;
                        if (cq < 25) {
                            #pragma unroll
                            for (int jc = 0; jc < 4; jc++) {
                                float w = fws[(cq * 4 + jc) * HID + kc * 50 + k];
                                acc[qi][jc][0] = fmaf(w, yv.x, acc[qi][jc][0]);
                                acc[qi][jc][1] = fmaf(w, yv.y, acc[qi][jc][1]);
                                acc[qi][jc][2] = fmaf(w, yv.z, acc[qi][jc][2]);
                                acc[qi][jc][3] = fmaf(w, yv.w, acc[qi][jc][3]);
                            }
                        }
                    }
                }
            }
            float* o = out + (size_t)t * BATCH * NCLS;
            #pragma unroll
            for (int qi = 0; qi < 2; qi++) {
                int cq = cg + 16 * qi;
                if (cq < 25) {
                    #pragma unroll
                    for (int jb = 0; jb < 4; jb++) {
                        float4 v = make_float4(acc[qi][0][jb], acc[qi][1][jb],
                                               acc[qi][2][jb], acc[qi][3][jb]);
                        *(float4*)(o + (bqf + jb) * NCLS + cq * 4) = v;
                    }
                }
            }
        }
    }

    // ---- reset-free counter cleanup ----
    __syncthreads();
    if (tid == 0) {
        bar_arrive(&g_ack);
        if (blockIdx.x == 0) {
            while (ld_acq(&g_ack) < NCTA) {}
            for (int i = 0; i < NBG; i++) *(volatile unsigned*)&g_bar[i * 32] = 0u;
            *(volatile unsigned*)&g_gbar = 0u;
            *(volatile unsigned*)&g_ack  = 0u;
        }
    }
}

extern "C" void kernel_launch(void* const* d_in, const int* in_sizes, int n_in,
                              void* d_out, int out_size)
{
    (void)in_sizes; (void)n_in; (void)out_size;
    const float* inp  = (const float*)d_in[0];
    const float* h0   = (const float*)d_in[1];
    const float* c0   = (const float*)d_in[2];
    const float* Wih0 = (const float*)d_in[3];
    const float* Whh0 = (const float*)d_in[4];
    const float* bih0 = (const float*)d_in[5];
    const float* bhh0 = (const float*)d_in[6];
    const float* Wih1 = (const float*)d_in[7];
    const float* Whh1 = (const float*)d_in[8];
    const float* bih1 = (const float*)d_in[9];
    const float* bhh1 = (const float*)d_in[10];
    const float* fcW  = (const float*)d_in[11];
    const float* fcb  = (const float*)d_in[12];
    float* out = (float*)d_out;

    cudaFuncSetAttribute(lstm_all_kernel,
                         cudaFuncAttributeMaxDynamicSharedMemorySize, SMEM_BYTES);
    lstm_all_kernel<<<NCTA, NTHR, SMEM_BYTES>>>(inp, h0, c0,
                                                Wih0, Whh0, bih0, bhh0,
                                                Wih1, Whh1, bih1, bhh1,
                                                fcW, fcb, out);
}